// round 1
// baseline (speedup 1.0000x reference)
#include <cuda_runtime.h>
#include <cuda_bf16.h>

#define NB       4096
#define NINPUTS  41024
#define NL1      128
#define NL2      32
#define NL3      32
#define CAP      2048
#define NTHREADS 512

// One block per batch row. Scans both perspective rows (w_in, b_in) with
// coalesced float4 loads, compacts active features to shared memory, gathers
// W_ft rows (L2-resident, 21 MB), then runs the tiny clipped MLP tail.
__global__ void __launch_bounds__(NTHREADS, 2) nnue_kernel(
    const float* __restrict__ us,   const float* __restrict__ them,
    const float* __restrict__ w_in, const float* __restrict__ b_in,
    const float* __restrict__ W_ft, const float* __restrict__ b_ft,
    const float* __restrict__ W1,   const float* __restrict__ b1,
    const float* __restrict__ W2,   const float* __restrict__ b2,
    const float* __restrict__ Wo,   const float* __restrict__ bo,
    float* __restrict__ out)
{
    __shared__ int   s_idx[CAP];
    __shared__ float s_val[CAP];
    __shared__ int   s_cnt;
    __shared__ float s_acc[2][NL1];   // feature-transformer accumulators (w, b)
    __shared__ float s_l0[2 * NL1];
    __shared__ float s_l1[NL2];
    __shared__ float s_l2[NL3];

    const int row = blockIdx.x;
    const int tid = threadIdx.x;

    // ---- Feature transformer: two perspectives, sequential (reuse buffers) ----
    #pragma unroll 1
    for (int p = 0; p < 2; ++p) {
        const float* src = (p == 0 ? w_in : b_in) + (size_t)row * NINPUTS;
        if (tid == 0) s_cnt = 0;
        __syncthreads();

        // Coalesced float4 scan of the 41024-float row (10256 float4s).
        const float4* src4 = (const float4*)src;
        const int n4 = NINPUTS / 4;
        for (int i = tid; i < n4; i += NTHREADS) {
            float4 v = src4[i];
            if (v.x != 0.f || v.y != 0.f || v.z != 0.f || v.w != 0.f) {
                if (v.x != 0.f) { int q = atomicAdd(&s_cnt, 1); if (q < CAP) { s_idx[q] = 4*i + 0; s_val[q] = v.x; } }
                if (v.y != 0.f) { int q = atomicAdd(&s_cnt, 1); if (q < CAP) { s_idx[q] = 4*i + 1; s_val[q] = v.y; } }
                if (v.z != 0.f) { int q = atomicAdd(&s_cnt, 1); if (q < CAP) { s_idx[q] = 4*i + 2; s_val[q] = v.z; } }
                if (v.w != 0.f) { int q = atomicAdd(&s_cnt, 1); if (q < CAP) { s_idx[q] = 4*i + 3; s_val[q] = v.w; } }
            }
        }
        __syncthreads();

        const int cnt = min(s_cnt, CAP);
        // 128 threads: thread j accumulates output dim j. For each feature f,
        // threads 0..127 read W_ft[idx*128 + j] -> contiguous 512B, coalesced,
        // L2-hit after first touch (W_ft = 21 MB < 126 MB L2).
        if (tid < NL1) {
            float a = b_ft[tid];
            #pragma unroll 4
            for (int f = 0; f < cnt; ++f) {
                a += s_val[f] * W_ft[(size_t)s_idx[f] * NL1 + tid];
            }
            s_acc[p][tid] = a;
        }
        __syncthreads();   // protect s_idx/s_val/s_cnt reuse and s_acc
    }

    // ---- l0: perspective select + clip [0,1] ----
    const float u = us[row];
    const float t = them[row];
    if (tid < 2 * NL1) {
        const int j = tid;
        const float wv = (j < NL1) ? s_acc[0][j] : s_acc[1][j - NL1];
        const float bv = (j < NL1) ? s_acc[1][j] : s_acc[0][j - NL1];
        float v = u * wv + t * bv;
        s_l0[j] = fminf(fmaxf(v, 0.f), 1.f);
    }
    __syncthreads();

    // ---- l1 = clip(l0 @ W1 + b1), W1: [256, 32] ----
    if (tid < NL2) {
        float a = b1[tid];
        #pragma unroll 8
        for (int i = 0; i < 2 * NL1; ++i)
            a += s_l0[i] * W1[i * NL2 + tid];
        s_l1[tid] = fminf(fmaxf(a, 0.f), 1.f);
    }
    __syncthreads();

    // ---- l2 = clip(l1 @ W2 + b2), W2: [32, 32] ----
    if (tid < NL3) {
        float a = b2[tid];
        #pragma unroll
        for (int i = 0; i < NL2; ++i)
            a += s_l1[i] * W2[i * NL3 + tid];
        s_l2[tid] = fminf(fmaxf(a, 0.f), 1.f);
    }
    __syncthreads();

    // ---- out = l2 @ Wo + bo (warp 0 reduction) ----
    if (tid < 32) {
        float a = s_l2[tid] * Wo[tid];
        #pragma unroll
        for (int off = 16; off > 0; off >>= 1)
            a += __shfl_down_sync(0xffffffffu, a, off);
        if (tid == 0) out[row] = a + bo[0];
    }
}

extern "C" void kernel_launch(void* const* d_in, const int* in_sizes, int n_in,
                              void* d_out, int out_size) {
    // metadata order: us, them, w_in, b_in, W_ft, b_ft, W1, b1, W2, b2, Wo, bo
    const float* us   = (const float*)d_in[0];
    const float* them = (const float*)d_in[1];
    const float* w_in = (const float*)d_in[2];
    const float* b_in = (const float*)d_in[3];
    const float* W_ft = (const float*)d_in[4];
    const float* b_ft = (const float*)d_in[5];
    const float* W1   = (const float*)d_in[6];
    const float* b1   = (const float*)d_in[7];
    const float* W2   = (const float*)d_in[8];
    const float* b2   = (const float*)d_in[9];
    const float* Wo   = (const float*)d_in[10];
    const float* bo   = (const float*)d_in[11];
    float* out = (float*)d_out;

    nnue_kernel<<<NB, NTHREADS>>>(us, them, w_in, b_in, W_ft, b_ft,
                                  W1, b1, W2, b2, Wo, bo, out);
}

// round 2
// speedup vs baseline: 1.9347x; 1.9347x over previous
#include <cuda_runtime.h>
#include <cuda_bf16.h>

#define NB       4096
#define NINPUTS  41024
#define N4       (NINPUTS / 4)     // 10256 float4 per perspective row
#define TOT4     (2 * N4)          // 20512 combined (w then b)
#define NL1      128
#define NL2      32
#define NL3      32
#define CAP      1024
#define NTHREADS 512
#define U        8                 // float4 loads in flight per thread

// One block per batch row. Fused scan of both perspective rows with explicit
// 8-deep load batching (MLP=8) and streaming (.cs) hints; ballot-free sparse
// compaction via rare shared atomics; 4-way parallel gather of L2-resident
// W_ft rows; tiny clipped-MLP tail.
__global__ void __launch_bounds__(NTHREADS, 2) nnue_kernel(
    const float* __restrict__ us,   const float* __restrict__ them,
    const float* __restrict__ w_in, const float* __restrict__ b_in,
    const float* __restrict__ W_ft, const float* __restrict__ b_ft,
    const float* __restrict__ W1,   const float* __restrict__ b1,
    const float* __restrict__ W2,   const float* __restrict__ b2,
    const float* __restrict__ Wo,   const float* __restrict__ bo,
    float* __restrict__ out)
{
    __shared__ int   s_e[CAP];          // (p<<16) | feature index
    __shared__ float s_v[CAP];
    __shared__ int   s_cnt;
    __shared__ float s_pw[4][NL1];      // per-group partial accumulators
    __shared__ float s_pb[4][NL1];
    __shared__ float s_acc[2][NL1];
    __shared__ float s_l0[2 * NL1];
    __shared__ float s_l1[NL2];
    __shared__ float s_l2[NL3];

    const int row = blockIdx.x;
    const int tid = threadIdx.x;

    const float4* __restrict__ w4 = (const float4*)(w_in + (size_t)row * NINPUTS);
    const float4* __restrict__ b4 = (const float4*)(b_in + (size_t)row * NINPUTS);

    if (tid == 0) s_cnt = 0;
    __syncthreads();

    // ---- Fused scan: both perspectives, 8 loads in flight per thread ----
    #pragma unroll 1
    for (int base = 0; base < TOT4; base += NTHREADS * U) {
        float4 v[U];
        #pragma unroll
        for (int u = 0; u < U; ++u) {
            const int i = base + u * NTHREADS + tid;
            if (i < TOT4) {
                const float4* p4 = (i < N4) ? (w4 + i) : (b4 + (i - N4));
                v[u] = __ldcs(p4);       // evict-first: don't thrash W_ft in L2
            } else {
                v[u] = make_float4(0.f, 0.f, 0.f, 0.f);
            }
        }
        #pragma unroll
        for (int u = 0; u < U; ++u) {
            const float4 vv = v[u];
            if (vv.x != 0.f || vv.y != 0.f || vv.z != 0.f || vv.w != 0.f) {
                const int i   = base + u * NTHREADS + tid;
                const int p   = (i >= N4);
                const int col = (i - p * N4) * 4;
                const int tag = p << 16;
                if (vv.x != 0.f) { int q = atomicAdd(&s_cnt, 1); if (q < CAP) { s_e[q] = tag | (col + 0); s_v[q] = vv.x; } }
                if (vv.y != 0.f) { int q = atomicAdd(&s_cnt, 1); if (q < CAP) { s_e[q] = tag | (col + 1); s_v[q] = vv.y; } }
                if (vv.z != 0.f) { int q = atomicAdd(&s_cnt, 1); if (q < CAP) { s_e[q] = tag | (col + 2); s_v[q] = vv.z; } }
                if (vv.w != 0.f) { int q = atomicAdd(&s_cnt, 1); if (q < CAP) { s_e[q] = tag | (col + 3); s_v[q] = vv.w; } }
            }
        }
    }
    __syncthreads();

    // ---- Gather W_ft rows: 4 groups x 128 threads, strided features ----
    {
        const int cnt = min(s_cnt, CAP);
        const int j = tid & (NL1 - 1);     // output dim
        const int g = tid >> 7;            // group 0..3
        float aw = 0.f, ab = 0.f;
        #pragma unroll 2
        for (int f = g; f < cnt; f += 4) {
            const int   e   = s_e[f];
            const int   idx = e & 0xFFFF;
            const float val = s_v[f];
            const float prod = val * W_ft[idx * NL1 + j];   // coalesced, L2-hit
            if (e & (1 << 16)) ab += prod; else aw += prod;
        }
        s_pw[g][j] = aw;
        s_pb[g][j] = ab;
    }
    __syncthreads();

    if (tid < 2 * NL1) {
        const int p = tid >> 7;
        const int j = tid & (NL1 - 1);
        const float* part = p ? &s_pb[0][0] : &s_pw[0][0];
        float a = b_ft[j];
        #pragma unroll
        for (int g = 0; g < 4; ++g) a += part[g * NL1 + j];
        s_acc[p][j] = a;
    }
    __syncthreads();

    // ---- l0: perspective select + clip [0,1] ----
    const float u = us[row];
    const float t = them[row];
    if (tid < 2 * NL1) {
        const int j = tid;
        const float wv = (j < NL1) ? s_acc[0][j] : s_acc[1][j - NL1];
        const float bv = (j < NL1) ? s_acc[1][j] : s_acc[0][j - NL1];
        const float v = u * wv + t * bv;
        s_l0[j] = fminf(fmaxf(v, 0.f), 1.f);
    }
    __syncthreads();

    // ---- l1 = clip(l0 @ W1 + b1), W1: [256, 32] ----
    if (tid < NL2) {
        float a = b1[tid];
        #pragma unroll 8
        for (int i = 0; i < 2 * NL1; ++i)
            a += s_l0[i] * W1[i * NL2 + tid];
        s_l1[tid] = fminf(fmaxf(a, 0.f), 1.f);
    }
    __syncthreads();

    // ---- l2 = clip(l1 @ W2 + b2), W2: [32, 32] ----
    if (tid < NL3) {
        float a = b2[tid];
        #pragma unroll
        for (int i = 0; i < NL2; ++i)
            a += s_l1[i] * W2[i * NL3 + tid];
        s_l2[tid] = fminf(fmaxf(a, 0.f), 1.f);
    }
    __syncthreads();

    // ---- out = l2 @ Wo + bo (warp 0 reduction) ----
    if (tid < 32) {
        float a = s_l2[tid] * Wo[tid];
        #pragma unroll
        for (int off = 16; off > 0; off >>= 1)
            a += __shfl_down_sync(0xffffffffu, a, off);
        if (tid == 0) out[row] = a + bo[0];
    }
}

extern "C" void kernel_launch(void* const* d_in, const int* in_sizes, int n_in,
                              void* d_out, int out_size) {
    const float* us   = (const float*)d_in[0];
    const float* them = (const float*)d_in[1];
    const float* w_in = (const float*)d_in[2];
    const float* b_in = (const float*)d_in[3];
    const float* W_ft = (const float*)d_in[4];
    const float* b_ft = (const float*)d_in[5];
    const float* W1   = (const float*)d_in[6];
    const float* b1   = (const float*)d_in[7];
    const float* W2   = (const float*)d_in[8];
    const float* b2   = (const float*)d_in[9];
    const float* Wo   = (const float*)d_in[10];
    const float* bo   = (const float*)d_in[11];
    float* out = (float*)d_out;

    nnue_kernel<<<NB, NTHREADS>>>(us, them, w_in, b_in, W_ft, b_ft,
                                  W1, b1, W2, b2, Wo, bo, out);
}

// round 3
// speedup vs baseline: 2.4471x; 1.2648x over previous
#include <cuda_runtime.h>
#include <cuda_bf16.h>

#define NB       4096
#define NINPUTS  41024
#define N4       (NINPUTS / 4)     // 10256 float4 per perspective row
#define VROWS    (2 * NB)          // 8192 (row, perspective) virtual rows
#define NL1      128
#define NL2      32
#define NL3      32
#define CAPS     192               // shared compaction headroom
#define CAP2     128               // persisted entries per virtual row
#define SCAN_T   256
#define U        8                 // float4 loads in flight per thread
#define SCAN_B   740               // 148 SMs * 5 resident blocks

// Scratch lists: ~30 active features per virtual row, cap 128 (18-sigma margin).
__device__ int   g_cnt[VROWS];
__device__ int   g_idx[VROWS][CAP2];
__device__ float g_val[VROWS][CAP2];

// ---------------- Kernel 1: pure streaming scan + compaction ----------------
// Persistent blocks; each iteration scans one 164KB perspective row with 8
// loads in flight per thread and writes the compacted (idx,val) list.
__global__ void __launch_bounds__(SCAN_T, 5) scan_kernel(
    const float* __restrict__ w_in, const float* __restrict__ b_in)
{
    __shared__ int   s_cnt;
    __shared__ int   s_i[CAPS];
    __shared__ float s_v[CAPS];

    const int tid = threadIdx.x;

    for (int vr = blockIdx.x; vr < VROWS; vr += gridDim.x) {
        const int row = vr >> 1;
        const float4* __restrict__ s4 =
            (const float4*)(((vr & 1) ? b_in : w_in) + (size_t)row * NINPUTS);

        if (tid == 0) s_cnt = 0;
        __syncthreads();

        #pragma unroll 1
        for (int base = 0; base < N4; base += SCAN_T * U) {
            float4 v[U];
            #pragma unroll
            for (int u = 0; u < U; ++u) {
                const int i = base + u * SCAN_T + tid;
                v[u] = (i < N4) ? __ldcs(s4 + i) : make_float4(0.f, 0.f, 0.f, 0.f);
            }
            #pragma unroll
            for (int u = 0; u < U; ++u) {
                const float4 vv = v[u];
                if (vv.x != 0.f || vv.y != 0.f || vv.z != 0.f || vv.w != 0.f) {
                    const int col = (base + u * SCAN_T + tid) * 4;
                    if (vv.x != 0.f) { int q = atomicAdd(&s_cnt, 1); if (q < CAPS) { s_i[q] = col + 0; s_v[q] = vv.x; } }
                    if (vv.y != 0.f) { int q = atomicAdd(&s_cnt, 1); if (q < CAPS) { s_i[q] = col + 1; s_v[q] = vv.y; } }
                    if (vv.z != 0.f) { int q = atomicAdd(&s_cnt, 1); if (q < CAPS) { s_i[q] = col + 2; s_v[q] = vv.z; } }
                    if (vv.w != 0.f) { int q = atomicAdd(&s_cnt, 1); if (q < CAPS) { s_i[q] = col + 3; s_v[q] = vv.w; } }
                }
            }
        }
        __syncthreads();

        const int cnt = min(s_cnt, CAP2);
        if (tid == 0) g_cnt[vr] = cnt;
        if (tid < cnt) { g_idx[vr][tid] = s_i[tid]; g_val[vr][tid] = s_v[tid]; }
        __syncthreads();   // protect s_cnt/s_i/s_v before next iteration
    }
}

// ---------------- Kernel 2: W_ft gather (L2-resident) + clipped MLP ----------------
__global__ void __launch_bounds__(256, 8) mlp_kernel(
    const float* __restrict__ us,   const float* __restrict__ them,
    const float* __restrict__ W_ft, const float* __restrict__ b_ft,
    const float* __restrict__ W1,   const float* __restrict__ b1,
    const float* __restrict__ W2,   const float* __restrict__ b2,
    const float* __restrict__ Wo,   const float* __restrict__ bo,
    float* __restrict__ out)
{
    __shared__ int   s_i[2][CAP2];
    __shared__ float s_v[2][CAP2];
    __shared__ float s_acc[2][NL1];
    __shared__ float s_l0[2 * NL1];
    __shared__ float s_p1[8][NL2];
    __shared__ float s_l1[NL2];
    __shared__ float s_l2[NL3];

    const int row = blockIdx.x;
    const int tid = threadIdx.x;
    const int p   = tid >> 7;          // perspective group (0: w, 1: b)
    const int j   = tid & (NL1 - 1);   // output dim within group

    const int vr    = row * 2 + p;
    const int cnt_p = g_cnt[vr];

    if (j < cnt_p) { s_i[p][j] = g_idx[vr][j]; s_v[p][j] = g_val[vr][j]; }
    __syncthreads();

    // Gather: 128 threads per perspective, thread j owns output dim j.
    // Each feature reads a contiguous 512B slice of W_ft (L2-hit, 21MB table).
    {
        float a = b_ft[j];
        #pragma unroll 4
        for (int f = 0; f < cnt_p; ++f)
            a += s_v[p][f] * W_ft[s_i[p][f] * NL1 + j];
        s_acc[p][j] = a;
    }
    __syncthreads();

    // l0: perspective select + clip [0,1]
    const float u = us[row];
    const float t = them[row];
    {
        const float wv = (tid < NL1) ? s_acc[0][tid] : s_acc[1][tid - NL1];
        const float bv = (tid < NL1) ? s_acc[1][tid] : s_acc[0][tid - NL1];
        const float v = u * wv + t * bv;
        s_l0[tid] = fminf(fmaxf(v, 0.f), 1.f);
    }
    __syncthreads();

    // l1 = clip(l0 @ W1 + b1): 8 segments x 32 outputs
    {
        const int seg = tid >> 5;       // 0..7, inputs [seg*32, seg*32+32)
        const int o   = tid & 31;
        float a = 0.f;
        #pragma unroll
        for (int i = 0; i < 32; ++i)
            a += s_l0[seg * 32 + i] * W1[(seg * 32 + i) * NL2 + o];
        s_p1[seg][o] = a;
    }
    __syncthreads();
    if (tid < NL2) {
        float a = b1[tid];
        #pragma unroll
        for (int g = 0; g < 8; ++g) a += s_p1[g][tid];
        s_l1[tid] = fminf(fmaxf(a, 0.f), 1.f);
    }
    __syncthreads();

    // l2 = clip(l1 @ W2 + b2)
    if (tid < NL3) {
        float a = b2[tid];
        #pragma unroll
        for (int i = 0; i < NL2; ++i)
            a += s_l1[i] * W2[i * NL3 + tid];
        s_l2[tid] = fminf(fmaxf(a, 0.f), 1.f);
    }
    __syncthreads();

    // out = l2 @ Wo + bo
    if (tid < 32) {
        float a = s_l2[tid] * Wo[tid];
        #pragma unroll
        for (int off = 16; off > 0; off >>= 1)
            a += __shfl_down_sync(0xffffffffu, a, off);
        if (tid == 0) out[row] = a + bo[0];
    }
}

extern "C" void kernel_launch(void* const* d_in, const int* in_sizes, int n_in,
                              void* d_out, int out_size) {
    const float* us   = (const float*)d_in[0];
    const float* them = (const float*)d_in[1];
    const float* w_in = (const float*)d_in[2];
    const float* b_in = (const float*)d_in[3];
    const float* W_ft = (const float*)d_in[4];
    const float* b_ft = (const float*)d_in[5];
    const float* W1   = (const float*)d_in[6];
    const float* b1   = (const float*)d_in[7];
    const float* W2   = (const float*)d_in[8];
    const float* b2   = (const float*)d_in[9];
    const float* Wo   = (const float*)d_in[10];
    const float* bo   = (const float*)d_in[11];
    float* out = (float*)d_out;

    scan_kernel<<<SCAN_B, SCAN_T>>>(w_in, b_in);
    mlp_kernel<<<NB, 256>>>(us, them, W_ft, b_ft, W1, b1, W2, b2, Wo, bo, out);
}